// round 14
// baseline (speedup 1.0000x reference)
#include <cuda_runtime.h>

#define MAXN 100000
#define DFEAT 64

// Scratch (allocation-free): message accumulator, degree, hidden layer output.
__device__ __align__(16) float g_msg[MAXN * DFEAT];
__device__ __align__(16) float g_deg[MAXN];
__device__ __align__(16) float g_h[MAXN * DFEAT];

__device__ __forceinline__ void ffma2(unsigned long long& acc,
                                      unsigned long long a,
                                      unsigned long long b) {
    asm("fma.rn.f32x2 %0, %1, %2, %0;" : "+l"(acc) : "l"(a), "l"(b));
}
__device__ __forceinline__ unsigned long long packf2(float lo, float hi) {
    unsigned long long r;
    asm("mov.b64 %0, {%1, %2};" : "=l"(r) : "f"(lo), "f"(hi));
    return r;
}

// ---------------------------------------------------------------------------
// Zeroing kernel (graph memset nodes reject __device__ symbol memory).
// ---------------------------------------------------------------------------
__global__ void zero_kernel(float4* __restrict__ msg, float* __restrict__ deg,
                            int n4, int ndeg) {
    int i = blockIdx.x * blockDim.x + threadIdx.x;
    if (i < n4) msg[i] = make_float4(0.f, 0.f, 0.f, 0.f);
    if (deg != nullptr && i < ndeg) deg[i] = 0.f;
}

// ---------------------------------------------------------------------------
// Scatter: msg[dst] += feat[src] (+deg). 16 lanes per edge-GROUP, 4 edges per
// group: indices via one broadcast int4 load each, then 4 independent
// coalesced LDG.128 gathers (MLP=4) followed by 4 float4 vector atomics.
// ---------------------------------------------------------------------------
__global__ void scatter_kernel(const float* __restrict__ feat,
                               const int* __restrict__ src,
                               const int* __restrict__ dst,
                               float* __restrict__ msg,
                               float* __restrict__ deg,
                               int E) {
    int tid = blockIdx.x * blockDim.x + threadIdx.x;
    int g = tid >> 4;
    int c = tid & 15;
    int e0 = g * 4;
    if (e0 >= E) return;
    const float4* f4 = reinterpret_cast<const float4*>(feat);
    float4* m4 = reinterpret_cast<float4*>(msg);
    if (e0 + 3 < E) {
        int4 s4 = *reinterpret_cast<const int4*>(src + e0);  // broadcast
        int4 d4 = *reinterpret_cast<const int4*>(dst + e0);  // broadcast
        float4 v0 = f4[s4.x * 16 + c];
        float4 v1 = f4[s4.y * 16 + c];
        float4 v2 = f4[s4.z * 16 + c];
        float4 v3 = f4[s4.w * 16 + c];
        atomicAdd(m4 + d4.x * 16 + c, v0);
        atomicAdd(m4 + d4.y * 16 + c, v1);
        atomicAdd(m4 + d4.z * 16 + c, v2);
        atomicAdd(m4 + d4.w * 16 + c, v3);
        if (deg != nullptr && c == 0) {
            atomicAdd(deg + d4.x, 1.0f);
            atomicAdd(deg + d4.y, 1.0f);
            atomicAdd(deg + d4.z, 1.0f);
            atomicAdd(deg + d4.w, 1.0f);
        }
    } else {
        for (int e = e0; e < E; e++) {
            int s = src[e], d = dst[e];
            float4 v = f4[s * 16 + c];
            atomicAdd(m4 + d * 16 + c, v);
            if (deg != nullptr && c == 0) atomicAdd(deg + d, 1.0f);
        }
    }
}

// ---------------------------------------------------------------------------
// Fused SAGE layer: out = (msg/max(deg,1)) @ Wl + bl + xin @ Wr
//   RELU   : apply relu, store hidden [N,64]
//   CLS    : fuse classifier out2 = h2 @ Wc + bc  [N,2] (h2 never stored)
//   ZEROMSG: zero this block's 32 msg rows after consuming them
// 256 threads, 32 rows/block, 48KB static smem. Weights stay ROW-MAJOR [k][c]
// (conflict-free stride-1 LDS across lanes); packed f32x2 W operands are built
// with two scalar LDS + mov.b64 pack. Mainloop FMA-issue = 32 FFMA2 per k4
// (vs 64 scalar FFMA), A/X pairs come free from float4 row loads.
// ---------------------------------------------------------------------------
template <bool RELU, bool CLS, bool ZEROMSG>
__global__ __launch_bounds__(256) void layer_kernel(
    const float* __restrict__ msg, const float* __restrict__ deg,
    const float* __restrict__ xin,
    const float* __restrict__ Wl, const float* __restrict__ bl,
    const float* __restrict__ Wr,
    const float* __restrict__ Wc, const float* __restrict__ bc,
    float* __restrict__ hout, float* __restrict__ out2,
    float* __restrict__ msgz, int N)
{
    __shared__ float sWl[64 * 64];
    __shared__ float sWr[64 * 64];
    __shared__ float sA[32 * 64];
    __shared__ float sX[32 * 64];

    int tid = threadIdx.x;
    int rowbase = blockIdx.x * 32;

    for (int i = tid; i < 1024; i += 256) {
        reinterpret_cast<float4*>(sWl)[i] = reinterpret_cast<const float4*>(Wl)[i];
        reinterpret_cast<float4*>(sWr)[i] = reinterpret_cast<const float4*>(Wr)[i];
    }

    for (int i = tid; i < 512; i += 256) {
        int r = i >> 4;
        int row = rowbase + r;
        if (row >= N) row = N - 1;
        int gi = row * 16 + (i & 15);
        float4 a = reinterpret_cast<const float4*>(msg)[gi];
        float inv = 1.0f / fmaxf(deg[row], 1.0f);
        a.x *= inv; a.y *= inv; a.z *= inv; a.w *= inv;
        reinterpret_cast<float4*>(sA)[i] = a;
        reinterpret_cast<float4*>(sX)[i] = reinterpret_cast<const float4*>(xin)[gi];
    }
    __syncthreads();

    // msg rows consumed -> zero them for the next scatter (overlaps mainloop).
    if (ZEROMSG) {
        float4 z4 = make_float4(0.f, 0.f, 0.f, 0.f);
        for (int i = tid; i < 512; i += 256) {
            int row = rowbase + (i >> 4);
            if (row < N)
                reinterpret_cast<float4*>(msgz)[row * 16 + (i & 15)] = z4;
        }
    }

    int tx = tid & 31;        // lane -> output columns tx, tx+32
    int ty = tid >> 5;        // warp -> rows ty*4 .. ty*4+3
    int c0 = tx, c1 = tx + 32;
    int ty4 = ty * 4;

    // acc[rr][cc]: f32x2 (even-k partial lo, odd-k partial hi)
    unsigned long long acc[4][2];
#pragma unroll
    for (int rr = 0; rr < 4; rr++) { acc[rr][0] = 0ull; acc[rr][1] = 0ull; }

#pragma unroll
    for (int k4 = 0; k4 < 64; k4 += 4) {
        ulonglong2 av[4], xv[4];
#pragma unroll
        for (int rr = 0; rr < 4; rr++) {
            av[rr] = *reinterpret_cast<const ulonglong2*>(&sA[(ty4 + rr) * 64 + k4]);
            xv[rr] = *reinterpret_cast<const ulonglong2*>(&sX[(ty4 + rr) * 64 + k4]);
        }
#pragma unroll
        for (int p = 0; p < 2; p++) {
            int k = k4 + 2 * p;
            unsigned long long wl0 = packf2(sWl[k * 64 + c0], sWl[(k + 1) * 64 + c0]);
            unsigned long long wl1 = packf2(sWl[k * 64 + c1], sWl[(k + 1) * 64 + c1]);
            unsigned long long wr0 = packf2(sWr[k * 64 + c0], sWr[(k + 1) * 64 + c0]);
            unsigned long long wr1 = packf2(sWr[k * 64 + c1], sWr[(k + 1) * 64 + c1]);
#pragma unroll
            for (int rr = 0; rr < 4; rr++) {
                unsigned long long a  = p ? av[rr].y : av[rr].x;
                unsigned long long x2 = p ? xv[rr].y : xv[rr].x;
                ffma2(acc[rr][0], a, wl0);
                ffma2(acc[rr][0], x2, wr0);
                ffma2(acc[rr][1], a, wl1);
                ffma2(acc[rr][1], x2, wr1);
            }
        }
    }

    float bias0 = bl[c0], bias1 = bl[c1];
    float h0[4], h1[4];
#pragma unroll
    for (int rr = 0; rr < 4; rr++) {
        float lo, hi;
        asm("mov.b64 {%0, %1}, %2;" : "=f"(lo), "=f"(hi) : "l"(acc[rr][0]));
        h0[rr] = lo + hi + bias0;
        asm("mov.b64 {%0, %1}, %2;" : "=f"(lo), "=f"(hi) : "l"(acc[rr][1]));
        h1[rr] = lo + hi + bias1;
    }

    if (RELU) {
#pragma unroll
        for (int rr = 0; rr < 4; rr++) {
            int row = rowbase + ty4 + rr;
            if (row < N) {
                hout[row * 64 + c0] = fmaxf(h0[rr], 0.0f);
                hout[row * 64 + c1] = fmaxf(h1[rr], 0.0f);
            }
        }
    }
    if (CLS) {
        float wc00 = Wc[c0 * 2 + 0], wc01 = Wc[c0 * 2 + 1];
        float wc10 = Wc[c1 * 2 + 0], wc11 = Wc[c1 * 2 + 1];
#pragma unroll
        for (int rr = 0; rr < 4; rr++) {
            float p0 = h0[rr] * wc00 + h1[rr] * wc10;
            float p1 = h0[rr] * wc01 + h1[rr] * wc11;
#pragma unroll
            for (int off = 16; off > 0; off >>= 1) {
                p0 += __shfl_down_sync(0xffffffffu, p0, off);
                p1 += __shfl_down_sync(0xffffffffu, p1, off);
            }
            if (tx == 0) {
                int row = rowbase + ty4 + rr;
                if (row < N) {
                    out2[row * 2 + 0] = p0 + bc[0];
                    out2[row * 2 + 1] = p1 + bc[1];
                }
            }
        }
    }
}

extern "C" void kernel_launch(void* const* d_in, const int* in_sizes, int n_in,
                              void* d_out, int out_size) {
    const float* x   = (const float*)d_in[0];
    const int*   ei  = (const int*)d_in[1];     // int32 (JAX x64-disabled)
    const float* W1l = (const float*)d_in[2];
    const float* b1  = (const float*)d_in[3];
    const float* W1r = (const float*)d_in[4];
    const float* W2l = (const float*)d_in[5];
    const float* b2  = (const float*)d_in[6];
    const float* W2r = (const float*)d_in[7];
    const float* Wc  = (const float*)d_in[8];
    const float* bc  = (const float*)d_in[9];
    float*       out = (float*)d_out;

    int N = in_sizes[0] / DFEAT;
    int E = in_sizes[1] / 2;
    const int* src = ei;
    const int* dst = ei + E;

    float *msg, *deg, *h;
    cudaGetSymbolAddress((void**)&msg, g_msg);
    cudaGetSymbolAddress((void**)&deg, g_deg);
    cudaGetSymbolAddress((void**)&h,   g_h);

    int n4 = N * DFEAT / 4;
    int zgrid = (n4 + 255) / 256;
    long long sthreads = (((long long)E + 3) / 4) * 16;  // 4 edges per 16-lane group
    int sgrid = (int)((sthreads + 255) / 256);
    int lgrid = (N + 31) / 32;

    // Layer 1
    zero_kernel<<<zgrid, 256>>>((float4*)msg, deg, n4, N);
    scatter_kernel<<<sgrid, 256>>>(x, src, dst, msg, deg, E);
    layer_kernel<true, false, true><<<lgrid, 256>>>(
        msg, deg, x, W1l, b1, W1r, nullptr, nullptr, h, nullptr, msg, N);
    // Layer 2 (+ fused classifier); msg re-zeroed by layer 1, deg reused.
    scatter_kernel<<<sgrid, 256>>>(h, src, dst, msg, nullptr, E);
    layer_kernel<false, true, false><<<lgrid, 256>>>(
        msg, deg, h, W2l, b2, W2r, Wc, bc, nullptr, out, nullptr, N);
}

// round 15
// speedup vs baseline: 1.5119x; 1.5119x over previous
#include <cuda_runtime.h>

#define MAXN 100000
#define DFEAT 64

// Scratch (allocation-free): message accumulator, degree, hidden layer output.
__device__ __align__(16) float g_msg[MAXN * DFEAT];
__device__ __align__(16) float g_deg[MAXN];
__device__ __align__(16) float g_h[MAXN * DFEAT];

// ---------------------------------------------------------------------------
// Zeroing kernel (graph memset nodes reject __device__ symbol memory).
// ---------------------------------------------------------------------------
__global__ void zero_kernel(float4* __restrict__ msg, float* __restrict__ deg,
                            int n4, int ndeg) {
    int i = blockIdx.x * blockDim.x + threadIdx.x;
    if (i < n4) msg[i] = make_float4(0.f, 0.f, 0.f, 0.f);
    if (deg != nullptr && i < ndeg) deg[i] = 0.f;
}

// ---------------------------------------------------------------------------
// Scatter: msg[dst] += feat[src] (+deg). 16-lane group handles 2 edges:
// one broadcast int2 load per index role, 2 independent LDG.128 gathers
// (MLP=2), then 2 float4 vector atomics. Midpoint between MLP=1 (latency
// exposed) and MLP=4 (L1tex wavefront-queue contention, measured regression).
// ---------------------------------------------------------------------------
__global__ void scatter_kernel(const float* __restrict__ feat,
                               const int* __restrict__ src,
                               const int* __restrict__ dst,
                               float* __restrict__ msg,
                               float* __restrict__ deg,
                               int E) {
    int tid = blockIdx.x * blockDim.x + threadIdx.x;
    int g = tid >> 4;
    int c = tid & 15;
    int e0 = g * 2;
    if (e0 >= E) return;
    const float4* f4 = reinterpret_cast<const float4*>(feat);
    float4* m4 = reinterpret_cast<float4*>(msg);
    if (e0 + 1 < E) {
        int2 s2 = *reinterpret_cast<const int2*>(src + e0);  // broadcast
        int2 d2 = *reinterpret_cast<const int2*>(dst + e0);  // broadcast
        float4 v0 = f4[s2.x * 16 + c];
        float4 v1 = f4[s2.y * 16 + c];
        atomicAdd(m4 + d2.x * 16 + c, v0);
        atomicAdd(m4 + d2.y * 16 + c, v1);
        if (deg != nullptr && c == 0) {
            atomicAdd(deg + d2.x, 1.0f);
            atomicAdd(deg + d2.y, 1.0f);
        }
    } else {
        int s = src[e0], d = dst[e0];
        float4 v = f4[s * 16 + c];
        atomicAdd(m4 + d * 16 + c, v);
        if (deg != nullptr && c == 0) atomicAdd(deg + d, 1.0f);
    }
}

// ---------------------------------------------------------------------------
// Fused SAGE layer: out = (msg/max(deg,1)) @ Wl + bl + xin @ Wr
//   RELU   : apply relu, store hidden [N,64]
//   CLS    : fuse classifier out2 = h2 @ Wc + bc  [N,2] (h2 never stored)
//   ZEROMSG: zero this block's 32 consumed msg rows (replaces 2nd zero_kernel)
// Block: 256 threads, 32 node-rows. 48KB static smem. Scalar FFMA mainloop
// (measured faster than both f32x2 variants on this shape).
// ---------------------------------------------------------------------------
template <bool RELU, bool CLS, bool ZEROMSG>
__global__ __launch_bounds__(256) void layer_kernel(
    const float* __restrict__ msg, const float* __restrict__ deg,
    const float* __restrict__ xin,
    const float* __restrict__ Wl, const float* __restrict__ bl,
    const float* __restrict__ Wr,
    const float* __restrict__ Wc, const float* __restrict__ bc,
    float* __restrict__ hout, float* __restrict__ out2,
    float* __restrict__ msgz, int N)
{
    __shared__ float sWl[64 * 64];
    __shared__ float sWr[64 * 64];
    __shared__ float sA[32 * 64];
    __shared__ float sX[32 * 64];

    int tid = threadIdx.x;
    int rowbase = blockIdx.x * 32;

    // Load both weight matrices (row-major [k][c]) into shared.
    for (int i = tid; i < 1024; i += 256) {
        reinterpret_cast<float4*>(sWl)[i] = reinterpret_cast<const float4*>(Wl)[i];
        reinterpret_cast<float4*>(sWr)[i] = reinterpret_cast<const float4*>(Wr)[i];
    }

    // Activation tiles; scale msg by 1/max(deg,1) on the way in.
    for (int i = tid; i < 512; i += 256) {
        int r = i >> 4;
        int row = rowbase + r;
        if (row >= N) row = N - 1;
        int gi = row * 16 + (i & 15);
        float4 a = reinterpret_cast<const float4*>(msg)[gi];
        float inv = 1.0f / fmaxf(deg[row], 1.0f);
        a.x *= inv; a.y *= inv; a.z *= inv; a.w *= inv;
        reinterpret_cast<float4*>(sA)[i] = a;
        reinterpret_cast<float4*>(sX)[i] = reinterpret_cast<const float4*>(xin)[gi];
    }
    __syncthreads();

    // msg rows consumed -> zero them for the next scatter (overlaps mainloop).
    if (ZEROMSG) {
        float4 z4 = make_float4(0.f, 0.f, 0.f, 0.f);
        for (int i = tid; i < 512; i += 256) {
            int row = rowbase + (i >> 4);
            if (row < N)
                reinterpret_cast<float4*>(msgz)[row * 16 + (i & 15)] = z4;
        }
    }

    int tx = tid & 31;        // lane -> output columns tx, tx+32
    int ty = tid >> 5;        // warp -> rows ty*4 .. ty*4+3
    int c0 = tx, c1 = tx + 32;
    int ty4 = ty * 4;

    float bias0 = bl[c0], bias1 = bl[c1];
    float acc[4][2];
#pragma unroll
    for (int rr = 0; rr < 4; rr++) { acc[rr][0] = bias0; acc[rr][1] = bias1; }

#pragma unroll 4
    for (int k4 = 0; k4 < 64; k4 += 4) {
        float af[4][4], xf[4][4];
#pragma unroll
        for (int rr = 0; rr < 4; rr++) {
            *reinterpret_cast<float4*>(af[rr]) =
                *reinterpret_cast<const float4*>(&sA[(ty4 + rr) * 64 + k4]);
            *reinterpret_cast<float4*>(xf[rr]) =
                *reinterpret_cast<const float4*>(&sX[(ty4 + rr) * 64 + k4]);
        }
#pragma unroll
        for (int kk = 0; kk < 4; kk++) {
            float wl0 = sWl[(k4 + kk) * 64 + c0];
            float wl1 = sWl[(k4 + kk) * 64 + c1];
            float wr0 = sWr[(k4 + kk) * 64 + c0];
            float wr1 = sWr[(k4 + kk) * 64 + c1];
#pragma unroll
            for (int rr = 0; rr < 4; rr++) {
                acc[rr][0] += af[rr][kk] * wl0 + xf[rr][kk] * wr0;
                acc[rr][1] += af[rr][kk] * wl1 + xf[rr][kk] * wr1;
            }
        }
    }

    if (RELU) {
#pragma unroll
        for (int rr = 0; rr < 4; rr++) {
            int row = rowbase + ty4 + rr;
            if (row < N) {
                hout[row * 64 + c0] = fmaxf(acc[rr][0], 0.0f);
                hout[row * 64 + c1] = fmaxf(acc[rr][1], 0.0f);
            }
        }
    }
    if (CLS) {
        float wc00 = Wc[c0 * 2 + 0], wc01 = Wc[c0 * 2 + 1];
        float wc10 = Wc[c1 * 2 + 0], wc11 = Wc[c1 * 2 + 1];
#pragma unroll
        for (int rr = 0; rr < 4; rr++) {
            float p0 = acc[rr][0] * wc00 + acc[rr][1] * wc10;
            float p1 = acc[rr][0] * wc01 + acc[rr][1] * wc11;
#pragma unroll
            for (int off = 16; off > 0; off >>= 1) {
                p0 += __shfl_down_sync(0xffffffffu, p0, off);
                p1 += __shfl_down_sync(0xffffffffu, p1, off);
            }
            if (tx == 0) {
                int row = rowbase + ty4 + rr;
                if (row < N) {
                    out2[row * 2 + 0] = p0 + bc[0];
                    out2[row * 2 + 1] = p1 + bc[1];
                }
            }
        }
    }
}

extern "C" void kernel_launch(void* const* d_in, const int* in_sizes, int n_in,
                              void* d_out, int out_size) {
    const float* x   = (const float*)d_in[0];
    const int*   ei  = (const int*)d_in[1];     // int32 (JAX x64-disabled)
    const float* W1l = (const float*)d_in[2];
    const float* b1  = (const float*)d_in[3];
    const float* W1r = (const float*)d_in[4];
    const float* W2l = (const float*)d_in[5];
    const float* b2  = (const float*)d_in[6];
    const float* W2r = (const float*)d_in[7];
    const float* Wc  = (const float*)d_in[8];
    const float* bc  = (const float*)d_in[9];
    float*       out = (float*)d_out;

    int N = in_sizes[0] / DFEAT;
    int E = in_sizes[1] / 2;
    const int* src = ei;
    const int* dst = ei + E;

    float *msg, *deg, *h;
    cudaGetSymbolAddress((void**)&msg, g_msg);
    cudaGetSymbolAddress((void**)&deg, g_deg);
    cudaGetSymbolAddress((void**)&h,   g_h);

    int n4 = N * DFEAT / 4;
    int zgrid = (n4 + 255) / 256;
    long long sthreads = (((long long)E + 1) / 2) * 16;  // 2 edges per 16-lane group
    int sgrid = (int)((sthreads + 255) / 256);
    int lgrid = (N + 31) / 32;

    // Layer 1
    zero_kernel<<<zgrid, 256>>>((float4*)msg, deg, n4, N);
    scatter_kernel<<<sgrid, 256>>>(x, src, dst, msg, deg, E);
    layer_kernel<true, false, true><<<lgrid, 256>>>(
        msg, deg, x, W1l, b1, W1r, nullptr, nullptr, h, nullptr, msg, N);
    // Layer 2 (+ fused classifier); msg re-zeroed by layer 1, deg reused.
    scatter_kernel<<<sgrid, 256>>>(h, src, dst, msg, nullptr, E);
    layer_kernel<false, true, false><<<lgrid, 256>>>(
        msg, deg, h, W2l, b2, W2r, Wc, bc, nullptr, out, nullptr, N);
}

// round 17
// speedup vs baseline: 1.5189x; 1.0046x over previous
#include <cuda_runtime.h>
#include <cuda_fp16.h>

#define MAXN 100000
#define DFEAT 64

// Scratch (allocation-free): message accumulator, degree, hidden output,
// fp16 shadow copies of the two gather sources.
__device__ __align__(16) float  g_msg[MAXN * DFEAT];
__device__ __align__(16) float  g_deg[MAXN];
__device__ __align__(16) float  g_h[MAXN * DFEAT];
__device__ __align__(16) __half g_xh[MAXN * DFEAT];
__device__ __align__(16) __half g_hh[MAXN * DFEAT];

__device__ __forceinline__ float4 h4_to_f4(uint2 r) {
    __half2 a = *reinterpret_cast<__half2*>(&r.x);
    __half2 b = *reinterpret_cast<__half2*>(&r.y);
    float2 fa = __half22float2(a), fb = __half22float2(b);
    return make_float4(fa.x, fa.y, fb.x, fb.y);
}

// ---------------------------------------------------------------------------
// Prep kernel: zero msg + deg, and convert x -> fp16 shadow (same index
// space: n4 float4s cover both msg and x).
// ---------------------------------------------------------------------------
__global__ void prep_kernel(const float4* __restrict__ x, uint2* __restrict__ xh,
                            float4* __restrict__ msg, float* __restrict__ deg,
                            int n4, int ndeg) {
    int i = blockIdx.x * blockDim.x + threadIdx.x;
    if (i < n4) {
        msg[i] = make_float4(0.f, 0.f, 0.f, 0.f);
        float4 v = x[i];
        __half2 h01 = __floats2half2_rn(v.x, v.y);
        __half2 h23 = __floats2half2_rn(v.z, v.w);
        uint2 u;
        u.x = *reinterpret_cast<unsigned*>(&h01);
        u.y = *reinterpret_cast<unsigned*>(&h23);
        xh[i] = u;
    }
    if (i < ndeg) deg[i] = 0.f;
}

// ---------------------------------------------------------------------------
// Scatter: msg[dst] += feat16[src] (+deg). 16-lane group handles 2 edges
// (MLP=2, measured sweet spot). Gather source is fp16 (8B/lane -> one 128B
// line per edge, half the read traffic); accumulation stays fp32 float4.
// ---------------------------------------------------------------------------
__global__ void scatter_kernel(const __half* __restrict__ feat,
                               const int* __restrict__ src,
                               const int* __restrict__ dst,
                               float* __restrict__ msg,
                               float* __restrict__ deg,
                               int E) {
    int tid = blockIdx.x * blockDim.x + threadIdx.x;
    int g = tid >> 4;
    int c = tid & 15;
    int e0 = g * 2;
    if (e0 >= E) return;
    const uint2* f2 = reinterpret_cast<const uint2*>(feat);  // row stride 16
    float4* m4 = reinterpret_cast<float4*>(msg);
    if (e0 + 1 < E) {
        int2 s2 = *reinterpret_cast<const int2*>(src + e0);  // broadcast
        int2 d2 = *reinterpret_cast<const int2*>(dst + e0);  // broadcast
        uint2 r0 = f2[s2.x * 16 + c];
        uint2 r1 = f2[s2.y * 16 + c];
        atomicAdd(m4 + d2.x * 16 + c, h4_to_f4(r0));
        atomicAdd(m4 + d2.y * 16 + c, h4_to_f4(r1));
        if (deg != nullptr && c == 0) {
            atomicAdd(deg + d2.x, 1.0f);
            atomicAdd(deg + d2.y, 1.0f);
        }
    } else {
        int s = src[e0], d = dst[e0];
        uint2 r = f2[s * 16 + c];
        atomicAdd(m4 + d * 16 + c, h4_to_f4(r));
        if (deg != nullptr && c == 0) atomicAdd(deg + d, 1.0f);
    }
}

// ---------------------------------------------------------------------------
// Fused SAGE layer: out = (msg/max(deg,1)) @ Wl + bl + xin @ Wr
//   RELU   : relu, store hidden fp32 [N,64] AND fp16 shadow (layer-2 gather)
//   CLS    : fuse classifier out2 = h2 @ Wc + bc  [N,2] (h2 never stored)
//   ZEROMSG: zero this block's 32 consumed msg rows (replaces 2nd zero pass)
// 256 threads, 32 rows/block, 48KB static smem, scalar FFMA mainloop.
// ---------------------------------------------------------------------------
template <bool RELU, bool CLS, bool ZEROMSG>
__global__ __launch_bounds__(256) void layer_kernel(
    const float* __restrict__ msg, const float* __restrict__ deg,
    const float* __restrict__ xin,
    const float* __restrict__ Wl, const float* __restrict__ bl,
    const float* __restrict__ Wr,
    const float* __restrict__ Wc, const float* __restrict__ bc,
    float* __restrict__ hout, __half* __restrict__ hout16,
    float* __restrict__ out2, float* __restrict__ msgz, int N)
{
    __shared__ float sWl[64 * 64];
    __shared__ float sWr[64 * 64];
    __shared__ float sA[32 * 64];
    __shared__ float sX[32 * 64];

    int tid = threadIdx.x;
    int rowbase = blockIdx.x * 32;

    for (int i = tid; i < 1024; i += 256) {
        reinterpret_cast<float4*>(sWl)[i] = reinterpret_cast<const float4*>(Wl)[i];
        reinterpret_cast<float4*>(sWr)[i] = reinterpret_cast<const float4*>(Wr)[i];
    }

    for (int i = tid; i < 512; i += 256) {
        int r = i >> 4;
        int row = rowbase + r;
        if (row >= N) row = N - 1;
        int gi = row * 16 + (i & 15);
        float4 a = reinterpret_cast<const float4*>(msg)[gi];
        float inv = 1.0f / fmaxf(deg[row], 1.0f);
        a.x *= inv; a.y *= inv; a.z *= inv; a.w *= inv;
        reinterpret_cast<float4*>(sA)[i] = a;
        reinterpret_cast<float4*>(sX)[i] = reinterpret_cast<const float4*>(xin)[gi];
    }
    __syncthreads();

    // msg rows consumed -> zero them for the next scatter (overlaps mainloop).
    if (ZEROMSG) {
        float4 z4 = make_float4(0.f, 0.f, 0.f, 0.f);
        for (int i = tid; i < 512; i += 256) {
            int row = rowbase + (i >> 4);
            if (row < N)
                reinterpret_cast<float4*>(msgz)[row * 16 + (i & 15)] = z4;
        }
    }

    int tx = tid & 31;        // lane -> output columns tx, tx+32
    int ty = tid >> 5;        // warp -> rows ty*4 .. ty*4+3
    int c0 = tx, c1 = tx + 32;
    int ty4 = ty * 4;

    float bias0 = bl[c0], bias1 = bl[c1];
    float acc[4][2];
#pragma unroll
    for (int rr = 0; rr < 4; rr++) { acc[rr][0] = bias0; acc[rr][1] = bias1; }

#pragma unroll 4
    for (int k4 = 0; k4 < 64; k4 += 4) {
        float af[4][4], xf[4][4];
#pragma unroll
        for (int rr = 0; rr < 4; rr++) {
            *reinterpret_cast<float4*>(af[rr]) =
                *reinterpret_cast<const float4*>(&sA[(ty4 + rr) * 64 + k4]);
            *reinterpret_cast<float4*>(xf[rr]) =
                *reinterpret_cast<const float4*>(&sX[(ty4 + rr) * 64 + k4]);
        }
#pragma unroll
        for (int kk = 0; kk < 4; kk++) {
            float wl0 = sWl[(k4 + kk) * 64 + c0];
            float wl1 = sWl[(k4 + kk) * 64 + c1];
            float wr0 = sWr[(k4 + kk) * 64 + c0];
            float wr1 = sWr[(k4 + kk) * 64 + c1];
#pragma unroll
            for (int rr = 0; rr < 4; rr++) {
                acc[rr][0] += af[rr][kk] * wl0 + xf[rr][kk] * wr0;
                acc[rr][1] += af[rr][kk] * wl1 + xf[rr][kk] * wr1;
            }
        }
    }

    if (RELU) {
#pragma unroll
        for (int rr = 0; rr < 4; rr++) {
            int row = rowbase + ty4 + rr;
            if (row < N) {
                float r0 = fmaxf(acc[rr][0], 0.0f);
                float r1 = fmaxf(acc[rr][1], 0.0f);
                hout[row * 64 + c0] = r0;
                hout[row * 64 + c1] = r1;
                hout16[row * 64 + c0] = __float2half_rn(r0);
                hout16[row * 64 + c1] = __float2half_rn(r1);
            }
        }
    }
    if (CLS) {
        float wc00 = Wc[c0 * 2 + 0], wc01 = Wc[c0 * 2 + 1];
        float wc10 = Wc[c1 * 2 + 0], wc11 = Wc[c1 * 2 + 1];
#pragma unroll
        for (int rr = 0; rr < 4; rr++) {
            float p0 = acc[rr][0] * wc00 + acc[rr][1] * wc10;
            float p1 = acc[rr][0] * wc01 + acc[rr][1] * wc11;
#pragma unroll
            for (int off = 16; off > 0; off >>= 1) {
                p0 += __shfl_down_sync(0xffffffffu, p0, off);
                p1 += __shfl_down_sync(0xffffffffu, p1, off);
            }
            if (tx == 0) {
                int row = rowbase + ty4 + rr;
                if (row < N) {
                    out2[row * 2 + 0] = p0 + bc[0];
                    out2[row * 2 + 1] = p1 + bc[1];
                }
            }
        }
    }
}

extern "C" void kernel_launch(void* const* d_in, const int* in_sizes, int n_in,
                              void* d_out, int out_size) {
    const float* x   = (const float*)d_in[0];
    const int*   ei  = (const int*)d_in[1];     // int32 (JAX x64-disabled)
    const float* W1l = (const float*)d_in[2];
    const float* b1  = (const float*)d_in[3];
    const float* W1r = (const float*)d_in[4];
    const float* W2l = (const float*)d_in[5];
    const float* b2  = (const float*)d_in[6];
    const float* W2r = (const float*)d_in[7];
    const float* Wc  = (const float*)d_in[8];
    const float* bc  = (const float*)d_in[9];
    float*       out = (float*)d_out;

    int N = in_sizes[0] / DFEAT;
    int E = in_sizes[1] / 2;
    const int* src = ei;
    const int* dst = ei + E;

    float *msg, *deg, *h;
    __half *xh, *hh;
    cudaGetSymbolAddress((void**)&msg, g_msg);
    cudaGetSymbolAddress((void**)&deg, g_deg);
    cudaGetSymbolAddress((void**)&h,   g_h);
    cudaGetSymbolAddress((void**)&xh,  g_xh);
    cudaGetSymbolAddress((void**)&hh,  g_hh);

    int n4 = N * DFEAT / 4;
    int zgrid = (n4 + 255) / 256;
    long long sthreads = (((long long)E + 1) / 2) * 16;  // 2 edges / 16-lane group
    int sgrid = (int)((sthreads + 255) / 256);
    int lgrid = (N + 31) / 32;

    // Layer 1 (gather from fp16 shadow of x; fp32 accumulation)
    prep_kernel<<<zgrid, 256>>>((const float4*)x, (uint2*)xh,
                                (float4*)msg, deg, n4, N);
    scatter_kernel<<<sgrid, 256>>>(xh, src, dst, msg, deg, E);
    layer_kernel<true, false, true><<<lgrid, 256>>>(
        msg, deg, x, W1l, b1, W1r, nullptr, nullptr, h, hh, nullptr, msg, N);
    // Layer 2 (+ fused classifier); msg re-zeroed by layer 1, deg reused.
    scatter_kernel<<<sgrid, 256>>>(hh, src, dst, msg, nullptr, E);
    layer_kernel<false, true, false><<<lgrid, 256>>>(
        msg, deg, h, W2l, b2, W2r, Wc, bc, nullptr, nullptr, out, nullptr, N);
}